// round 2
// baseline (speedup 1.0000x reference)
#include <cuda_runtime.h>

#define BATCH 32
#define NH    16
#define DK    64
#define DM    1024
#define TC    4096

// Scratch (device globals — no allocation allowed in kernel_launch)
__device__ float g_qp[BATCH * DM];   // scaled query projection
__device__ float g_kp[BATCH * DM];   // new-token key projection
__device__ float g_vp[BATCH * DM];   // new-token value projection
__device__ float g_x [BATCH * DM];   // attention output (pre out-proj)

// ---------------------------------------------------------------------------
// GEMV projection: out[b][j] = (sum_k act[b][k] * W[j][k] + bias[j]) * scale
// mode 0: QKV — act = act_ext (q input), grid.y selects {wq->g_qp(*qscale),
//                 wk->g_kp, wv->g_vp}
// mode 1: out-projection — act = g_x (device-side symbol!), W0/B0 -> out_ext
// CTA = 128 threads = 4 warps; warp computes 2 rows for all 32 batches,
// weights register-resident, activations L1/L2-resident, butterfly reduce.
// ---------------------------------------------------------------------------
__global__ void proj_kernel(int mode,
                            const float* __restrict__ act_ext,
                            const float* __restrict__ W0, const float* __restrict__ B0,
                            const float* __restrict__ W1, const float* __restrict__ B1,
                            const float* __restrict__ W2, const float* __restrict__ B2,
                            float* __restrict__ out_ext,
                            float qscale)
{
    const float* act;
    const float* W;
    const float* bias;
    float* out;
    float scale = 1.0f;

    if (mode == 1) {
        act = g_x;  W = W0; bias = B0; out = out_ext;
    } else {
        act = act_ext;
        if (blockIdx.y == 0)      { W = W0; bias = B0; out = g_qp; scale = qscale; }
        else if (blockIdx.y == 1) { W = W1; bias = B1; out = g_kp; }
        else                      { W = W2; bias = B2; out = g_vp; }
    }

    const int warp = threadIdx.x >> 5;
    const int lane = threadIdx.x & 31;
    const int j0   = (blockIdx.x * 4 + warp) * 2;   // 2 rows per warp

    // Load 2 weight rows into registers: lane covers k = c*128 + lane*4 .. +3
    float4 w[2][8];
#pragma unroll
    for (int r = 0; r < 2; r++) {
        const float* Wr = W + (size_t)(j0 + r) * DM;
#pragma unroll
        for (int c = 0; c < 8; c++)
            w[r][c] = *(const float4*)(Wr + c * 128 + lane * 4);
    }

    for (int b = 0; b < BATCH; b++) {
        const float* ab = act + b * DM;
        float a0 = 0.0f, a1 = 0.0f;
#pragma unroll
        for (int c = 0; c < 8; c++) {
            float4 q4 = *(const float4*)(ab + c * 128 + lane * 4);
            a0 += q4.x * w[0][c].x + q4.y * w[0][c].y
                + q4.z * w[0][c].z + q4.w * w[0][c].w;
            a1 += q4.x * w[1][c].x + q4.y * w[1][c].y
                + q4.z * w[1][c].z + q4.w * w[1][c].w;
        }
#pragma unroll
        for (int off = 16; off; off >>= 1) {
            a0 += __shfl_xor_sync(0xffffffffu, a0, off);
            a1 += __shfl_xor_sync(0xffffffffu, a1, off);
        }
        if (lane < 2) {
            float a = (lane == 0) ? a0 : a1;
            out[b * DM + j0 + lane] = (a + bias[j0 + lane]) * scale;
        }
    }
}

// ---------------------------------------------------------------------------
// Flash-decode attention over 4096 cached keys + 1 new token.
// One CTA per (b,h): 512 CTAs x 256 threads (8 warps).
// Each warp owns a contiguous 512-key chunk; lanes span DK via float2
// (coalesced 256B per row). Online softmax in registers (2 dims/lane).
// 4-key unroll -> 8 loads in flight before first use.
// Warp 0 additionally folds in the newly-projected k/v token.
// Cross-warp combine via smem. Writes g_x[b][h*64+d].
// ---------------------------------------------------------------------------
__global__ void attn_kernel(const float* __restrict__ Kc,
                            const float* __restrict__ Vc)
{
    const int bh   = blockIdx.x;       // 0..511
    const int b    = bh >> 4;
    const int h    = bh & 15;
    const int warp = threadIdx.x >> 5;
    const int lane = threadIdx.x & 31;

    __shared__ float sq[DK];
    __shared__ float sm[8], sl[8];
    __shared__ float so[8][DK];

    if (threadIdx.x < DK)
        sq[threadIdx.x] = g_qp[b * DM + h * DK + threadIdx.x];  // pre-scaled by 1/8
    __syncthreads();

    const float qa = sq[2 * lane];
    const float qb = sq[2 * lane + 1];

    const float* Kb = Kc + (size_t)bh * TC * DK;
    const float* Vb = Vc + (size_t)bh * TC * DK;

    float m  = -1e30f;
    float l  = 0.0f;
    float o0 = 0.0f, o1 = 0.0f;

    const int t0 = warp * (TC / 8);
    for (int t = t0; t < t0 + TC / 8; t += 4) {
        float2 kk[4], vv[4];
#pragma unroll
        for (int i = 0; i < 4; i++)
            kk[i] = *(const float2*)(Kb + (size_t)(t + i) * DK + 2 * lane);
#pragma unroll
        for (int i = 0; i < 4; i++)
            vv[i] = *(const float2*)(Vb + (size_t)(t + i) * DK + 2 * lane);
#pragma unroll
        for (int i = 0; i < 4; i++) {
            float s = kk[i].x * qa + kk[i].y * qb;
#pragma unroll
            for (int off = 16; off; off >>= 1)
                s += __shfl_xor_sync(0xffffffffu, s, off);
            float mn = fmaxf(m, s);
            float sc = __expf(m - mn);
            float p  = __expf(s - mn);
            l  = l  * sc + p;
            o0 = o0 * sc + p * vv[i].x;
            o1 = o1 * sc + p * vv[i].y;
            m  = mn;
        }
    }

    // New (appended) token: fold into warp 0's running state.
    if (warp == 0) {
        float2 kk = *(const float2*)(g_kp + b * DM + h * DK + 2 * lane);
        float2 vv = *(const float2*)(g_vp + b * DM + h * DK + 2 * lane);
        float s = kk.x * qa + kk.y * qb;
#pragma unroll
        for (int off = 16; off; off >>= 1)
            s += __shfl_xor_sync(0xffffffffu, s, off);
        float mn = fmaxf(m, s);
        float sc = __expf(m - mn);
        float p  = __expf(s - mn);
        l  = l  * sc + p;
        o0 = o0 * sc + p * vv.x;
        o1 = o1 * sc + p * vv.y;
        m  = mn;
    }

    if (lane == 0) { sm[warp] = m; sl[warp] = l; }
    so[warp][2 * lane]     = o0;
    so[warp][2 * lane + 1] = o1;
    __syncthreads();

    if (threadIdx.x < DK) {
        const int d = threadIdx.x;
        float M = sm[0];
#pragma unroll
        for (int w2 = 1; w2 < 8; w2++) M = fmaxf(M, sm[w2]);
        float L = 0.0f, O = 0.0f;
#pragma unroll
        for (int w2 = 0; w2 < 8; w2++) {
            float e = __expf(sm[w2] - M);
            L += e * sl[w2];
            O += e * so[w2][d];
        }
        g_x[b * DM + h * DK + d] = O / L;
    }
}

// ---------------------------------------------------------------------------
// inputs (metadata order): 0 q, 1 key_pre, 2 value_pre,
//   3 wq, 4 bq, 5 wk, 6 bk, 7 wv, 8 bv, 9 wo, 10 bo
// output: [32, 1, 1024] fp32
// ---------------------------------------------------------------------------
extern "C" void kernel_launch(void* const* d_in, const int* in_sizes, int n_in,
                              void* d_out, int out_size)
{
    const float* q   = (const float*)d_in[0];
    const float* Kc  = (const float*)d_in[1];
    const float* Vc  = (const float*)d_in[2];
    const float* wq  = (const float*)d_in[3];
    const float* bq  = (const float*)d_in[4];
    const float* wk  = (const float*)d_in[5];
    const float* bk  = (const float*)d_in[6];
    const float* wv  = (const float*)d_in[7];
    const float* bv  = (const float*)d_in[8];
    const float* wo  = (const float*)d_in[9];
    const float* bo  = (const float*)d_in[10];
    float* out = (float*)d_out;

    const float qscale = 0.125f;  // 1/sqrt(DK)

    // QKV projections (grid.y selects matrix; q gets the softmax scale folded in)
    proj_kernel<<<dim3(DM / 8, 3), 128>>>(0, q, wq, bq, wk, bk, wv, bv, nullptr, qscale);

    // Flash-decode attention over the cache + appended token
    attn_kernel<<<BATCH * NH, 256>>>(Kc, Vc);

    // Output projection: reads g_x via device-side symbol, writes d_out
    proj_kernel<<<dim3(DM / 8, 1), 128>>>(1, nullptr, wo, bo, nullptr, nullptr,
                                          nullptr, nullptr, out, 1.0f);
}

// round 3
// speedup vs baseline: 1.0321x; 1.0321x over previous
#include <cuda_runtime.h>

#define BATCH 32
#define NH    16
#define DK    64
#define DM    1024
#define TC    4096

// Scratch (device globals — no allocation allowed in kernel_launch)
__device__ float g_qp[BATCH * DM];   // scaled query projection
__device__ float g_kp[BATCH * DM];   // new-token key projection
__device__ float g_vp[BATCH * DM];   // new-token value projection
__device__ float g_x [BATCH * DM];   // attention output (pre out-proj)

// ---------------------------------------------------------------------------
// GEMV projection: out[b][j] = (sum_k act[b][k] * W[j][k] + bias[j]) * scale
// mode 0: QKV — act = act_ext (q input), grid.y selects {wq->g_qp(*qscale),
//                 wk->g_kp, wv->g_vp}
// mode 1: out-projection — act = g_x (device-side symbol), W0/B0 -> out_ext
//
// grid = (DM/8, nmat, 4): z splits the 32 batches into 4 groups of 8 so we get
// 4x the warp parallelism (weights re-read 4x but hit L2). Each warp computes
// 2 rows; inner loop processes 2 batches at once so the 4 shfl-reduce chains
// (26 cyc latency each) overlap instead of serializing.
// ---------------------------------------------------------------------------
__global__ void proj_kernel(int mode,
                            const float* __restrict__ act_ext,
                            const float* __restrict__ W0, const float* __restrict__ B0,
                            const float* __restrict__ W1, const float* __restrict__ B1,
                            const float* __restrict__ W2, const float* __restrict__ B2,
                            float* __restrict__ out_ext,
                            float qscale)
{
    const float* act;
    const float* W;
    const float* bias;
    float* out;
    float scale = 1.0f;

    if (mode == 1) {
        act = g_x;  W = W0; bias = B0; out = out_ext;
    } else {
        act = act_ext;
        if (blockIdx.y == 0)      { W = W0; bias = B0; out = g_qp; scale = qscale; }
        else if (blockIdx.y == 1) { W = W1; bias = B1; out = g_kp; }
        else                      { W = W2; bias = B2; out = g_vp; }
    }

    const int warp = threadIdx.x >> 5;
    const int lane = threadIdx.x & 31;
    const int j0   = (blockIdx.x * 4 + warp) * 2;   // 2 rows per warp
    const int b0   = blockIdx.z * 8;                // 8 batches per z-slice

    // Load 2 weight rows into registers: lane covers k = c*128 + lane*4 .. +3
    float4 w[2][8];
#pragma unroll
    for (int r = 0; r < 2; r++) {
        const float* Wr = W + (size_t)(j0 + r) * DM;
#pragma unroll
        for (int c = 0; c < 8; c++)
            w[r][c] = *(const float4*)(Wr + c * 128 + lane * 4);
    }

    const float bias0 = bias[j0], bias1 = bias[j0 + 1];

#pragma unroll
    for (int b = b0; b < b0 + 8; b += 2) {
        const float* ab0 = act + b * DM;
        const float* ab1 = act + (b + 1) * DM;
        float a0 = 0.0f, a1 = 0.0f, c0 = 0.0f, c1 = 0.0f;
#pragma unroll
        for (int c = 0; c < 8; c++) {
            float4 x0 = *(const float4*)(ab0 + c * 128 + lane * 4);
            float4 x1 = *(const float4*)(ab1 + c * 128 + lane * 4);
            a0 += x0.x * w[0][c].x + x0.y * w[0][c].y + x0.z * w[0][c].z + x0.w * w[0][c].w;
            a1 += x0.x * w[1][c].x + x0.y * w[1][c].y + x0.z * w[1][c].z + x0.w * w[1][c].w;
            c0 += x1.x * w[0][c].x + x1.y * w[0][c].y + x1.z * w[0][c].z + x1.w * w[0][c].w;
            c1 += x1.x * w[1][c].x + x1.y * w[1][c].y + x1.z * w[1][c].z + x1.w * w[1][c].w;
        }
#pragma unroll
        for (int off = 16; off; off >>= 1) {
            a0 += __shfl_xor_sync(0xffffffffu, a0, off);
            a1 += __shfl_xor_sync(0xffffffffu, a1, off);
            c0 += __shfl_xor_sync(0xffffffffu, c0, off);
            c1 += __shfl_xor_sync(0xffffffffu, c1, off);
        }
        if (lane == 0) {
            out[b * DM + j0]           = (a0 + bias0) * scale;
            out[b * DM + j0 + 1]       = (a1 + bias1) * scale;
            out[(b + 1) * DM + j0]     = (c0 + bias0) * scale;
            out[(b + 1) * DM + j0 + 1] = (c1 + bias1) * scale;
        }
    }
}

// ---------------------------------------------------------------------------
// Flash-decode attention over 4096 cached keys + 1 new token.
// One CTA per (b,h): 512 CTAs x 256 threads (8 warps).
// float4 / half-warp layout: 16 lanes cover DK=64 (4 dims/lane), so one
// LDG.128 instruction fetches one key per half-warp (2 keys per warp).
// Each half-warp maintains an INDEPENDENT online-softmax state over its
// (interleaved) key subsequence; score reduction is a 4-level shfl within
// the half. K/V loaded with __ldcs (streaming, zero reuse).
// 4 key-pairs unrolled -> 8 LDG.128 in flight per warp.
// Warp 0 / half 0 folds in the newly-projected token.
// Cross-(half)warp combine of 16 partial states via smem. Writes g_x.
// ---------------------------------------------------------------------------
__global__ void attn_kernel(const float* __restrict__ Kc,
                            const float* __restrict__ Vc)
{
    const int bh   = blockIdx.x;       // 0..511
    const int b    = bh >> 4;
    const int h    = bh & 15;
    const int warp = threadIdx.x >> 5;
    const int lane = threadIdx.x & 31;
    const int half = lane >> 4;        // 0 or 1
    const int li   = lane & 15;        // lane within half; dims 4*li..4*li+3

    __shared__ float4 sq[16];          // q, pre-scaled by 1/sqrt(DK)
    __shared__ float  sm[16], sl[16];
    __shared__ float4 so[16][16];

    if (threadIdx.x < 16)
        sq[threadIdx.x] = *(const float4*)(g_qp + b * DM + h * DK + 4 * threadIdx.x);
    __syncthreads();

    const float4 q4 = sq[li];

    const float* Kb = Kc + (size_t)bh * TC * DK;
    const float* Vb = Vc + (size_t)bh * TC * DK;

    float  m = -1e30f;
    float  l = 0.0f;
    float4 o = make_float4(0.f, 0.f, 0.f, 0.f);

    const int t0 = warp * (TC / 8);    // 512 keys per warp
    for (int t = t0; t < t0 + TC / 8; t += 8) {
        float4 kk[4], vv[4];
#pragma unroll
        for (int i = 0; i < 4; i++)
            kk[i] = __ldcs((const float4*)(Kb + (size_t)(t + 2 * i + half) * DK + 4 * li));
#pragma unroll
        for (int i = 0; i < 4; i++)
            vv[i] = __ldcs((const float4*)(Vb + (size_t)(t + 2 * i + half) * DK + 4 * li));
#pragma unroll
        for (int i = 0; i < 4; i++) {
            float s = kk[i].x * q4.x + kk[i].y * q4.y + kk[i].z * q4.z + kk[i].w * q4.w;
#pragma unroll
            for (int off = 8; off; off >>= 1)
                s += __shfl_xor_sync(0xffffffffu, s, off);   // stays within half
            float mn = fmaxf(m, s);
            float sc = __expf(m - mn);
            float p  = __expf(s - mn);
            l   = l   * sc + p;
            o.x = o.x * sc + p * vv[i].x;
            o.y = o.y * sc + p * vv[i].y;
            o.z = o.z * sc + p * vv[i].z;
            o.w = o.w * sc + p * vv[i].w;
            m   = mn;
        }
    }

    // New (appended) token: both halves of warp 0 compute the score (same
    // data), only half 0 folds it into its state (no shuffles in divergence).
    if (warp == 0) {
        float4 kk = *(const float4*)(g_kp + b * DM + h * DK + 4 * li);
        float4 vv = *(const float4*)(g_vp + b * DM + h * DK + 4 * li);
        float s = kk.x * q4.x + kk.y * q4.y + kk.z * q4.z + kk.w * q4.w;
#pragma unroll
        for (int off = 8; off; off >>= 1)
            s += __shfl_xor_sync(0xffffffffu, s, off);
        if (half == 0) {
            float mn = fmaxf(m, s);
            float sc = __expf(m - mn);
            float p  = __expf(s - mn);
            l   = l   * sc + p;
            o.x = o.x * sc + p * vv.x;
            o.y = o.y * sc + p * vv.y;
            o.z = o.z * sc + p * vv.z;
            o.w = o.w * sc + p * vv.w;
            m   = mn;
        }
    }

    const int idx = warp * 2 + half;   // 16 partial states
    if (li == 0) { sm[idx] = m; sl[idx] = l; }
    so[idx][li] = o;
    __syncthreads();

    // Combine 16 partial states; threads 0..63 each own one output dim.
    if (threadIdx.x < DK) {
        const int d = threadIdx.x;
        float M = sm[0];
#pragma unroll
        for (int i = 1; i < 16; i++) M = fmaxf(M, sm[i]);
        float L = 0.0f, O = 0.0f;
#pragma unroll
        for (int i = 0; i < 16; i++) {
            float e = __expf(sm[i] - M);
            L += e * sl[i];
            O += e * ((const float*)&so[i][d >> 2])[d & 3];
        }
        g_x[b * DM + h * DK + d] = O / L;
    }
}

// ---------------------------------------------------------------------------
// inputs (metadata order): 0 q, 1 key_pre, 2 value_pre,
//   3 wq, 4 bq, 5 wk, 6 bk, 7 wv, 8 bv, 9 wo, 10 bo
// output: [32, 1, 1024] fp32
// ---------------------------------------------------------------------------
extern "C" void kernel_launch(void* const* d_in, const int* in_sizes, int n_in,
                              void* d_out, int out_size)
{
    const float* q   = (const float*)d_in[0];
    const float* Kc  = (const float*)d_in[1];
    const float* Vc  = (const float*)d_in[2];
    const float* wq  = (const float*)d_in[3];
    const float* bq  = (const float*)d_in[4];
    const float* wk  = (const float*)d_in[5];
    const float* bk  = (const float*)d_in[6];
    const float* wv  = (const float*)d_in[7];
    const float* bv  = (const float*)d_in[8];
    const float* wo  = (const float*)d_in[9];
    const float* bo  = (const float*)d_in[10];
    float* out = (float*)d_out;

    const float qscale = 0.125f;  // 1/sqrt(DK)

    // QKV projections (grid.y selects matrix; q gets the softmax scale folded in)
    proj_kernel<<<dim3(DM / 8, 3, 4), 128>>>(0, q, wq, bq, wk, bk, wv, bv,
                                             nullptr, qscale);

    // Flash-decode attention over the cache + appended token
    attn_kernel<<<BATCH * NH, 256>>>(Kc, Vc);

    // Output projection: reads g_x via device-side symbol, writes d_out
    proj_kernel<<<dim3(DM / 8, 1, 4), 128>>>(1, nullptr, wo, bo, nullptr, nullptr,
                                             nullptr, nullptr, out, 1.0f);
}

// round 4
// speedup vs baseline: 1.2306x; 1.1923x over previous
#include <cuda_runtime.h>

#define BATCH 32
#define NH    16
#define DK    64
#define DM    1024
#define TC    4096

// Scratch (device globals — no allocation allowed in kernel_launch)
__device__ float g_qp[BATCH * DM];   // scaled query projection
__device__ float g_kp[BATCH * DM];   // new-token key projection
__device__ float g_vp[BATCH * DM];   // new-token value projection
__device__ float g_x [BATCH * DM];   // attention output (pre out-proj)

// ---------------------------------------------------------------------------
// GEMV projection: out[b][j] = (sum_k act[b][k] * W[j][k] + bias[j]) * scale
// mode 0: QKV — act = act_ext (q input), grid.y selects {wq->g_qp(*qscale),
//                 wk->g_kp, wv->g_vp}
// mode 1: out-projection — act = g_x (device-side symbol), W0/B0 -> out_ext
//
// grid = (DM/8, nmat, 8): z gives each CTA 4 batches; warp computes 2 rows x
// 4 batches = 8 accumulators whose shfl-reduce chains all interleave in one
// 5-level pass (no serialized batch loop). Weights re-read 8x but L2-hit.
// ---------------------------------------------------------------------------
__global__ void proj_kernel(int mode,
                            const float* __restrict__ act_ext,
                            const float* __restrict__ W0, const float* __restrict__ B0,
                            const float* __restrict__ W1, const float* __restrict__ B1,
                            const float* __restrict__ W2, const float* __restrict__ B2,
                            float* __restrict__ out_ext,
                            float qscale)
{
    const float* act;
    const float* W;
    const float* bias;
    float* out;
    float scale = 1.0f;

    if (mode == 1) {
        act = g_x;  W = W0; bias = B0; out = out_ext;
    } else {
        act = act_ext;
        if (blockIdx.y == 0)      { W = W0; bias = B0; out = g_qp; scale = qscale; }
        else if (blockIdx.y == 1) { W = W1; bias = B1; out = g_kp; }
        else                      { W = W2; bias = B2; out = g_vp; }
    }

    const int warp = threadIdx.x >> 5;
    const int lane = threadIdx.x & 31;
    const int j0   = (blockIdx.x * 4 + warp) * 2;   // 2 rows per warp
    const int b0   = blockIdx.z * 4;                // 4 batches per z-slice

    // Load 2 weight rows into registers: lane covers k = c*128 + lane*4 .. +3
    float4 w[2][8];
#pragma unroll
    for (int r = 0; r < 2; r++) {
        const float* Wr = W + (size_t)(j0 + r) * DM;
#pragma unroll
        for (int c = 0; c < 8; c++)
            w[r][c] = *(const float4*)(Wr + c * 128 + lane * 4);
    }

    // 8 accumulators: a[b][r], b = 0..3 local batch, r = 0..1 row
    float a[4][2];
#pragma unroll
    for (int b = 0; b < 4; b++) { a[b][0] = 0.0f; a[b][1] = 0.0f; }

#pragma unroll
    for (int c = 0; c < 8; c++) {
#pragma unroll
        for (int b = 0; b < 4; b++) {
            float4 x = *(const float4*)(act + (b0 + b) * DM + c * 128 + lane * 4);
            a[b][0] += x.x * w[0][c].x + x.y * w[0][c].y + x.z * w[0][c].z + x.w * w[0][c].w;
            a[b][1] += x.x * w[1][c].x + x.y * w[1][c].y + x.z * w[1][c].z + x.w * w[1][c].w;
        }
    }

    // One 5-level butterfly reduces all 8 chains (they interleave).
#pragma unroll
    for (int off = 16; off; off >>= 1) {
#pragma unroll
        for (int b = 0; b < 4; b++) {
            a[b][0] += __shfl_xor_sync(0xffffffffu, a[b][0], off);
            a[b][1] += __shfl_xor_sync(0xffffffffu, a[b][1], off);
        }
    }

    if (lane == 0) {
        const float bias0 = bias[j0], bias1 = bias[j0 + 1];
#pragma unroll
        for (int b = 0; b < 4; b++) {
            out[(b0 + b) * DM + j0]     = (a[b][0] + bias0) * scale;
            out[(b0 + b) * DM + j0 + 1] = (a[b][1] + bias1) * scale;
        }
    }
}

// ---------------------------------------------------------------------------
// Flash-decode attention over 4096 cached keys + 1 new token.
// One CTA per (b,h): 512 CTAs x 256 threads (8 warps).
// float4 / half-warp layout: 16 lanes cover DK=64 (4 dims/lane); one LDG.128
// fetches one key per half-warp (2 keys per warp). Each half-warp keeps an
// independent online-softmax state over its interleaved key subsequence.
//
// BLOCK-SOFTMAX: per 8-key block (per half), compute all 8 scores first
// (8 independent 4-level shfl chains interleave), reduce to a block max in
// registers, exp all 8 in parallel, accumulate sum_p and sum p_i*v_i with
// independent FMA chains, then do a SINGLE rescale of the running (m,l,o).
// 16 LDG.128 (8 K + 8 V) in flight per warp. K/V via __ldcs (streaming).
// ---------------------------------------------------------------------------
__global__ void attn_kernel(const float* __restrict__ Kc,
                            const float* __restrict__ Vc)
{
    const int bh   = blockIdx.x;       // 0..511
    const int b    = bh >> 4;
    const int h    = bh & 15;
    const int warp = threadIdx.x >> 5;
    const int lane = threadIdx.x & 31;
    const int half = lane >> 4;        // 0 or 1
    const int li   = lane & 15;        // lane within half; dims 4*li..4*li+3

    __shared__ float4 sq[16];          // q, pre-scaled by 1/sqrt(DK)
    __shared__ float  sm[16], sl[16];
    __shared__ float4 so[16][16];

    if (threadIdx.x < 16)
        sq[threadIdx.x] = *(const float4*)(g_qp + b * DM + h * DK + 4 * threadIdx.x);
    __syncthreads();

    const float4 q4 = sq[li];

    const float* Kb = Kc + (size_t)bh * TC * DK;
    const float* Vb = Vc + (size_t)bh * TC * DK;

    float  m = -1e30f;
    float  l = 0.0f;
    float4 o = make_float4(0.f, 0.f, 0.f, 0.f);

    const int t0 = warp * (TC / 8);    // 512 keys per warp, 8 per half per iter
    for (int t = t0; t < t0 + TC / 8; t += 16) {
        float4 kk[8], vv[8];
#pragma unroll
        for (int i = 0; i < 8; i++)
            kk[i] = __ldcs((const float4*)(Kb + (size_t)(t + 2 * i + half) * DK + 4 * li));
#pragma unroll
        for (int i = 0; i < 8; i++)
            vv[i] = __ldcs((const float4*)(Vb + (size_t)(t + 2 * i + half) * DK + 4 * li));

        // 8 scores; the 8 shfl-reduce chains interleave.
        float s[8];
#pragma unroll
        for (int i = 0; i < 8; i++)
            s[i] = kk[i].x * q4.x + kk[i].y * q4.y + kk[i].z * q4.z + kk[i].w * q4.w;
#pragma unroll
        for (int off = 8; off; off >>= 1)
#pragma unroll
            for (int i = 0; i < 8; i++)
                s[i] += __shfl_xor_sync(0xffffffffu, s[i], off);

        // Block max (register tree)
        float bm01 = fmaxf(s[0], s[1]), bm23 = fmaxf(s[2], s[3]);
        float bm45 = fmaxf(s[4], s[5]), bm67 = fmaxf(s[6], s[7]);
        float bm = fmaxf(fmaxf(bm01, bm23), fmaxf(bm45, bm67));
        float mn = fmaxf(m, bm);

        // 8 parallel exps + block accumulation (independent chains)
        float p[8];
#pragma unroll
        for (int i = 0; i < 8; i++) p[i] = __expf(s[i] - mn);

        float  lp = 0.0f;
        float4 op = make_float4(0.f, 0.f, 0.f, 0.f);
#pragma unroll
        for (int i = 0; i < 8; i++) {
            lp   += p[i];
            op.x += p[i] * vv[i].x;
            op.y += p[i] * vv[i].y;
            op.z += p[i] * vv[i].z;
            op.w += p[i] * vv[i].w;
        }

        // Single rescale of running state per 8-key block
        float sc = __expf(m - mn);
        l   = l   * sc + lp;
        o.x = o.x * sc + op.x;
        o.y = o.y * sc + op.y;
        o.z = o.z * sc + op.z;
        o.w = o.w * sc + op.w;
        m   = mn;
    }

    // New (appended) token: both halves of warp 0 compute the score (same
    // data), only half 0 folds it into its state.
    if (warp == 0) {
        float4 kk = *(const float4*)(g_kp + b * DM + h * DK + 4 * li);
        float4 vv = *(const float4*)(g_vp + b * DM + h * DK + 4 * li);
        float s = kk.x * q4.x + kk.y * q4.y + kk.z * q4.z + kk.w * q4.w;
#pragma unroll
        for (int off = 8; off; off >>= 1)
            s += __shfl_xor_sync(0xffffffffu, s, off);
        if (half == 0) {
            float mn = fmaxf(m, s);
            float sc = __expf(m - mn);
            float p  = __expf(s - mn);
            l   = l   * sc + p;
            o.x = o.x * sc + p * vv.x;
            o.y = o.y * sc + p * vv.y;
            o.z = o.z * sc + p * vv.z;
            o.w = o.w * sc + p * vv.w;
            m   = mn;
        }
    }

    const int idx = warp * 2 + half;   // 16 partial states
    if (li == 0) { sm[idx] = m; sl[idx] = l; }
    so[idx][li] = o;
    __syncthreads();

    // Combine 16 partial states; threads 0..63 each own one output dim.
    if (threadIdx.x < DK) {
        const int d = threadIdx.x;
        float M = sm[0];
#pragma unroll
        for (int i = 1; i < 16; i++) M = fmaxf(M, sm[i]);
        float L = 0.0f, O = 0.0f;
#pragma unroll
        for (int i = 0; i < 16; i++) {
            float e = __expf(sm[i] - M);
            L += e * sl[i];
            O += e * ((const float*)&so[i][d >> 2])[d & 3];
        }
        g_x[b * DM + h * DK + d] = O / L;
    }
}

// ---------------------------------------------------------------------------
// inputs (metadata order): 0 q, 1 key_pre, 2 value_pre,
//   3 wq, 4 bq, 5 wk, 6 bk, 7 wv, 8 bv, 9 wo, 10 bo
// output: [32, 1, 1024] fp32
// ---------------------------------------------------------------------------
extern "C" void kernel_launch(void* const* d_in, const int* in_sizes, int n_in,
                              void* d_out, int out_size)
{
    const float* q   = (const float*)d_in[0];
    const float* Kc  = (const float*)d_in[1];
    const float* Vc  = (const float*)d_in[2];
    const float* wq  = (const float*)d_in[3];
    const float* bq  = (const float*)d_in[4];
    const float* wk  = (const float*)d_in[5];
    const float* bk  = (const float*)d_in[6];
    const float* wv  = (const float*)d_in[7];
    const float* bv  = (const float*)d_in[8];
    const float* wo  = (const float*)d_in[9];
    const float* bo  = (const float*)d_in[10];
    float* out = (float*)d_out;

    const float qscale = 0.125f;  // 1/sqrt(DK)

    // QKV projections (grid.y selects matrix; q gets the softmax scale folded in)
    proj_kernel<<<dim3(DM / 8, 3, 8), 128>>>(0, q, wq, bq, wk, bk, wv, bv,
                                             nullptr, qscale);

    // Flash-decode attention over the cache + appended token
    attn_kernel<<<BATCH * NH, 256>>>(Kc, Vc);

    // Output projection: reads g_x via device-side symbol, writes d_out
    proj_kernel<<<dim3(DM / 8, 1, 8), 128>>>(1, nullptr, wo, bo, nullptr, nullptr,
                                             nullptr, nullptr, out, 1.0f);
}